// round 12
// baseline (speedup 1.0000x reference)
#include <cuda_runtime.h>
#include <cuda_bf16.h>
#include <cstdint>

// ---------------- problem constants ----------------
#define NN      32768
#define EE      131072
#define HH      512
#define HEH     128
#define H2      1024
#define OUTD    1024
#define BB      1024
#define NPG     32
#define EPG     128
#define LL      6
#define EPSV    1e-5f
#define NCOMBO  264

__device__ __constant__ int c_node_off[9] = {0,119,128,139,151,160,165,173,175};

// ---------------- scratch (device globals; no allocs allowed) ----------------
__device__ float g_z    [(size_t)NN * HH];
__device__ float g_h    [(size_t)NN * H2];
__device__ float g_zpre [(size_t)NN * HH];
__device__ float g_v    [OUTD + 1];
__device__ float g_w    [HH + 1];
__device__ float g_hgpre[(size_t)BB * OUTD];
__device__ float g_stats[8192];
__device__ float g_estats[LL * 2048];
__device__ int   g_combo[EE];
__device__ int   g_cnt  [NCOMBO];
__device__ float g_embu [NCOMBO * HEH];
__device__ float g_eeu  [(size_t)LL * NCOMBO * HH];
__device__ float g_eeact[(size_t)LL * NCOMBO * HH];
__device__ __nv_bfloat16 g_aggh[(size_t)NN * HH];
__device__ __nv_bfloat16 g_aggl[(size_t)NN * HH];
__device__ __nv_bfloat16 g_zh  [(size_t)NN * HH];
__device__ __nv_bfloat16 g_zl  [(size_t)NN * HH];
__device__ __nv_bfloat16 g_zgh [(size_t)BB * HH];
__device__ __nv_bfloat16 g_zgl [(size_t)BB * HH];
__device__ __nv_bfloat16 g_hgh [(size_t)BB * OUTD];
__device__ __nv_bfloat16 g_hgl [(size_t)BB * OUTD];
__device__ __nv_bfloat16 g_aW1h[(size_t)LL * H2 * HH];
__device__ __nv_bfloat16 g_aW1l[(size_t)LL * H2 * HH];
__device__ __nv_bfloat16 g_aW2h[(size_t)LL * HH * H2];
__device__ __nv_bfloat16 g_aW2l[(size_t)LL * HH * H2];
__device__ __nv_bfloat16 g_oWh [(size_t)OUTD * HH];
__device__ __nv_bfloat16 g_oWl [(size_t)OUTD * HH];
__device__ __nv_bfloat16 g_pWh [(size_t)OUTD * OUTD];
__device__ __nv_bfloat16 g_pWl [(size_t)OUTD * OUTD];

// ---------------- asm helpers ----------------
__device__ __forceinline__ uint32_t smem_u32(const void* p) {
    uint32_t a;
    asm("{ .reg .u64 t; cvta.to.shared.u64 t, %1; cvt.u32.u64 %0, t; }" : "=r"(a) : "l"(p));
    return a;
}
__device__ __forceinline__ void ldm_x4(uint32_t* r, uint32_t addr) {
    asm volatile("ldmatrix.sync.aligned.m8n8.x4.shared.b16 {%0,%1,%2,%3}, [%4];"
                 : "=r"(r[0]), "=r"(r[1]), "=r"(r[2]), "=r"(r[3]) : "r"(addr));
}
__device__ __forceinline__ void mma_bf16(float* c, const uint32_t* a, const uint32_t* b) {
    asm volatile("mma.sync.aligned.m16n8k16.row.col.f32.bf16.bf16.f32 "
                 "{%0,%1,%2,%3}, {%4,%5,%6,%7}, {%8,%9}, {%0,%1,%2,%3};"
                 : "+f"(c[0]), "+f"(c[1]), "+f"(c[2]), "+f"(c[3])
                 : "r"(a[0]), "r"(a[1]), "r"(a[2]), "r"(a[3]), "r"(b[0]), "r"(b[1]));
}
__device__ __forceinline__ void cpasync16(uint32_t sa, const void* ga) {
    asm volatile("cp.async.cg.shared.global [%0], [%1], 16;" :: "r"(sa), "l"(ga));
}
#define CP_COMMIT() asm volatile("cp.async.commit_group;" ::: "memory")
#define CP_WAIT1()  asm volatile("cp.async.wait_group 1;" ::: "memory")

__device__ __forceinline__ uint32_t pk(__nv_bfloat16 a, __nv_bfloat16 b) {
    return (uint32_t)__bfloat16_as_ushort(a) | ((uint32_t)__bfloat16_as_ushort(b) << 16);
}
__device__ __forceinline__ void split4(float4 v, uint2& hi, uint2& lo) {
    __nv_bfloat16 h0 = __float2bfloat16(v.x), h1 = __float2bfloat16(v.y);
    __nv_bfloat16 h2 = __float2bfloat16(v.z), h3 = __float2bfloat16(v.w);
    __nv_bfloat16 l0 = __float2bfloat16(v.x - __bfloat162float(h0));
    __nv_bfloat16 l1 = __float2bfloat16(v.y - __bfloat162float(h1));
    __nv_bfloat16 l2 = __float2bfloat16(v.z - __bfloat162float(h2));
    __nv_bfloat16 l3 = __float2bfloat16(v.w - __bfloat162float(h3));
    hi = make_uint2(pk(h0, h1), pk(h2, h3));
    lo = make_uint2(pk(l0, l1), pk(l2, l3));
}

// SMEM tile: 128 rows x 32 bf16 = 64B/row, XOR chunk swizzle
#define TILEB  (128 * 64)
#define STAGEB (4 * TILEB)
#define NSTAGE 3
#define GEMM_SMEM (NSTAGE * STAGEB)

__device__ __forceinline__ uint32_t swz(int row, int chunk) {
    return (uint32_t)(row * 64 + (((chunk + (row >> 1)) & 3) << 4));
}

// ---------------- tensor-core GEMM ----------------
// R10 config: 128x128 CTA, BK=32, 256 thr (8 warps 2x4, 64x32 warp tiles), 3-stage.
// SPLITA: A read as fp32 from Af; relu(x*bnp[k]+bnp[1024+k]) + bf16 hi/lo split
//         applied in registers during the A stage fill (LDG->STS), B via cp.async.
template <bool STATS, bool SPLITA>
__global__ void __launch_bounds__(256, 2)
gemm_mma(int N, int K,
         const __nv_bfloat16* __restrict__ Ah, const __nv_bfloat16* __restrict__ Al,
         const float* __restrict__ Af, const float* __restrict__ bnp,
         const __nv_bfloat16* __restrict__ Bh, const __nv_bfloat16* __restrict__ Bl,
         const float* __restrict__ bias, float* __restrict__ C,
         float* __restrict__ stats) {
    extern __shared__ char smem[];

    const int tid = threadIdx.x, lane = tid & 31, wid = tid >> 5;
    const int wr = wid >> 2, wc = wid & 3;
    const int brow = blockIdx.y, bcol = blockIdx.x;

    const size_t Kb = (size_t)K * 2;
    const char* pAh = SPLITA ? nullptr : (const char*)(Ah + (size_t)brow * 128 * K);
    const char* pAl = SPLITA ? nullptr : (const char*)(Al + (size_t)brow * 128 * K);
    const char* pBh = (const char*)(Bh + (size_t)bcol * 128 * K);
    const char* pBl = (const char*)(Bl + (size_t)bcol * 128 * K);
    const float* pAf = SPLITA ? (Af + (size_t)brow * 128 * K) : nullptr;

    const uint32_t ubase = smem_u32(smem);
    const int lr0 = tid >> 2, lc0 = tid & 3;
    const int lr1 = lr0 + 64, lc1 = lc0;
    const uint32_t so0 = swz(lr0, lc0), so1 = swz(lr1, lc1);

    auto issueB = [&](int k0, int s) {
        uint32_t base = ubase + s * STAGEB;
        size_t g0 = (size_t)lr0 * Kb + (size_t)k0 * 64 + lc0 * 16;
        size_t g1 = (size_t)lr1 * Kb + (size_t)k0 * 64 + lc1 * 16;
        cpasync16(base + 2 * TILEB + so0, pBh + g0);
        cpasync16(base + 2 * TILEB + so1, pBh + g1);
        cpasync16(base + 3 * TILEB + so0, pBl + g0);
        cpasync16(base + 3 * TILEB + so1, pBl + g1);
    };
    auto issueA = [&](int k0, int s) {   // non-SPLITA path
        uint32_t base = ubase + s * STAGEB;
        size_t g0 = (size_t)lr0 * Kb + (size_t)k0 * 64 + lc0 * 16;
        size_t g1 = (size_t)lr1 * Kb + (size_t)k0 * 64 + lc1 * 16;
        cpasync16(base + so0,         pAh + g0);
        cpasync16(base + so1,         pAh + g1);
        cpasync16(base + TILEB + so0, pAl + g0);
        cpasync16(base + TILEB + so1, pAl + g1);
    };

    // SPLITA machinery: 4 float4 / thread / tile
    const int far = tid >> 3;        // row base (0..31), +32*t
    const int fc4 = tid & 7;         // col chunk (col = fc4*4)
    float4 pa[4];
    float bsc[4], bsh[4];
    auto ldA = [&](int k0) {
#pragma unroll
        for (int t = 0; t < 4; t++)
            pa[t] = *(const float4*)(pAf + (size_t)(far + 32 * t) * K + k0 * 32 + fc4 * 4);
        int col = k0 * 32 + fc4 * 4;
#pragma unroll
        for (int i = 0; i < 4; i++) {
            bsc[i] = __ldg(&bnp[col + i]);
            bsh[i] = __ldg(&bnp[1024 + col + i]);
        }
    };
    auto stsA = [&](int s) {
        char* base = smem + s * STAGEB;
        uint32_t off0 = swz(far, fc4 >> 1) + (fc4 & 1) * 8;
#pragma unroll
        for (int t = 0; t < 4; t++) {
            float4 v = pa[t];
            v.x = fmaxf(0.f, v.x * bsc[0] + bsh[0]);
            v.y = fmaxf(0.f, v.y * bsc[1] + bsh[1]);
            v.z = fmaxf(0.f, v.z * bsc[2] + bsh[2]);
            v.w = fmaxf(0.f, v.w * bsc[3] + bsh[3]);
            uint2 hi, lo;
            split4(v, hi, lo);
            uint32_t off = swz(far + 32 * t, fc4 >> 1) + (fc4 & 1) * 8;
            *(uint2*)(base + off) = hi;
            *(uint2*)(base + TILEB + off) = lo;
        }
        (void)off0;
    };

    float acc[4][4][4];
#pragma unroll
    for (int i = 0; i < 4; i++)
#pragma unroll
        for (int j = 0; j < 4; j++)
#pragma unroll
            for (int q = 0; q < 4; q++) acc[i][j][q] = 0.f;

    const int a_row = (lane & 15);
    const int a_c   = (lane >> 4);
    const int b_row = (lane & 7) + ((lane >> 4) << 3);
    const int b_c   = ((lane >> 3) & 1);

    auto compute = [&](int s) {
        uint32_t uAh = ubase + s * STAGEB;
        uint32_t uAl = uAh + TILEB, uBh = uAl + TILEB, uBl = uBh + TILEB;
#pragma unroll
        for (int ks = 0; ks < 2; ks++) {
            uint32_t ah[4][4], al[4][4];
#pragma unroll
            for (int mt = 0; mt < 4; mt++) {
                int row = wr * 64 + mt * 16 + a_row;
                uint32_t off = swz(row, 2 * ks + a_c);
                ldm_x4(ah[mt], uAh + off);
                ldm_x4(al[mt], uAl + off);
            }
            uint32_t bh[4][2], bl[4][2];
#pragma unroll
            for (int np = 0; np < 2; np++) {
                int row = wc * 32 + np * 16 + b_row;
                uint32_t off = swz(row, 2 * ks + b_c);
                uint32_t r[4];
                ldm_x4(r, uBh + off);
                bh[np * 2][0] = r[0]; bh[np * 2][1] = r[1];
                bh[np * 2 + 1][0] = r[2]; bh[np * 2 + 1][1] = r[3];
                ldm_x4(r, uBl + off);
                bl[np * 2][0] = r[0]; bl[np * 2][1] = r[1];
                bl[np * 2 + 1][0] = r[2]; bl[np * 2 + 1][1] = r[3];
            }
#pragma unroll
            for (int mt = 0; mt < 4; mt++)
#pragma unroll
                for (int nt = 0; nt < 4; nt++) {
                    mma_bf16(acc[mt][nt], ah[mt], bh[nt]);
                    mma_bf16(acc[mt][nt], ah[mt], bl[nt]);
                    mma_bf16(acc[mt][nt], al[mt], bh[nt]);
                }
        }
    };

    const int nk = K >> 5;
    if (SPLITA) {
        ldA(0); stsA(0); issueB(0, 0); CP_COMMIT();
        ldA(1); stsA(1); issueB(1, 1); CP_COMMIT();
        if (nk > 2) ldA(2);
        CP_WAIT1();
        __syncthreads();
        int s = 0, snext = 2;
        for (int k = 0; k < nk; k++) {
            if (k + 2 < nk) { stsA(snext); issueB(k + 2, snext); }
            CP_COMMIT();
            compute(s);
            if (k + 3 < nk) ldA(k + 3);
            CP_WAIT1();
            __syncthreads();
            s = (s == 2) ? 0 : s + 1;
            snext = (snext == 2) ? 0 : snext + 1;
        }
    } else {
        issueA(0, 0); issueB(0, 0); CP_COMMIT();
        issueA(1, 1); issueB(1, 1); CP_COMMIT();
        CP_WAIT1();
        __syncthreads();
        int s = 0, snext = 2;
        for (int k = 0; k < nk; k++) {
            compute(s);
            if (k + 2 < nk) { issueA(k + 2, snext); issueB(k + 2, snext); }
            CP_COMMIT();
            CP_WAIT1();
            __syncthreads();
            s = (s == 2) ? 0 : s + 1;
            snext = (snext == 2) ? 0 : snext + 1;
        }
    }

    // ---- epilogue: bias, store, optional fused column stats ----
    float s1[8], s2[8];
    if (STATS) {
#pragma unroll
        for (int j = 0; j < 8; j++) { s1[j] = 0.f; s2[j] = 0.f; }
    }
#pragma unroll
    for (int mt = 0; mt < 4; mt++) {
        int row0 = brow * 128 + wr * 64 + mt * 16 + (lane >> 2);
#pragma unroll
        for (int nt = 0; nt < 4; nt++) {
            int col = bcol * 128 + wc * 32 + nt * 8 + (lane & 3) * 2;
            float b0 = bias[col], b1 = bias[col + 1];
            float v00 = acc[mt][nt][0] + b0, v01 = acc[mt][nt][1] + b1;
            float v10 = acc[mt][nt][2] + b0, v11 = acc[mt][nt][3] + b1;
            *(float2*)(C + (size_t)row0 * N + col) = make_float2(v00, v01);
            *(float2*)(C + (size_t)(row0 + 8) * N + col) = make_float2(v10, v11);
            if (STATS) {
                s1[nt * 2 + 0] += v00 + v10;
                s1[nt * 2 + 1] += v01 + v11;
                s2[nt * 2 + 0] += v00 * v00 + v10 * v10;
                s2[nt * 2 + 1] += v01 * v01 + v11 * v11;
            }
        }
    }
    if (STATS) {
#pragma unroll
        for (int j = 0; j < 8; j++) {
#pragma unroll
            for (int o = 4; o <= 16; o <<= 1) {
                s1[j] += __shfl_xor_sync(0xffffffffu, s1[j], o);
                s2[j] += __shfl_xor_sync(0xffffffffu, s2[j], o);
            }
        }
        if (lane < 4) {
#pragma unroll
            for (int nt = 0; nt < 4; nt++) {
#pragma unroll
                for (int p = 0; p < 2; p++) {
                    int col = bcol * 128 + wc * 32 + nt * 8 + lane * 2 + p;
                    atomicAdd(&stats[col], s1[nt * 2 + p]);
                    atomicAdd(&stats[1024 + col], s2[nt * 2 + p]);
                }
            }
        }
    }
}

// ---------------- per-graph aggregation (global gathers, 2 CTA/SM) ----------------
template <bool BN>
__global__ void __launch_bounds__(512, 2)
graph_aggregate(const float* __restrict__ zsrc, const float* __restrict__ bnp,
                const float* __restrict__ eeact,
                const int* __restrict__ eidx, const int* __restrict__ combo,
                __nv_bfloat16* __restrict__ aggh, __nv_bfloat16* __restrict__ aggl) {
    extern __shared__ float sagg[];
    __shared__ int s_src[EPG], s_dst[EPG], s_u[EPG];

    const int b = blockIdx.x;
    const int tid = threadIdx.x;

    float sc = 1.f, sh = 0.f;
    if (BN) { sc = bnp[tid]; sh = bnp[1024 + tid]; }

    if (tid < EPG) {
        s_src[tid] = eidx[b * EPG + tid] - b * NPG;
        s_dst[tid] = eidx[EE + b * EPG + tid] - b * NPG;
        s_u[tid]   = combo[b * EPG + tid];
    }
    const float* zb = zsrc + (size_t)b * NPG * HH;
#pragma unroll
    for (int n = 0; n < NPG; n++) {
        float v = zb[n * HH + tid];
        if (BN) v = fmaxf(0.f, v * sc + sh);
        sagg[n * HH + tid] = v;
    }
    __syncthreads();

    float zv = __ldg(&zb[s_src[0] * HH + tid]);
    float ev = __ldg(&eeact[(size_t)s_u[0] * HH + tid]);
#pragma unroll 4
    for (int e = 0; e < EPG; e++) {
        float zcur = zv;
        if (BN) zcur = fmaxf(0.f, zcur * sc + sh);
        float cur = zcur + ev;
        int d = s_dst[e];
        if (e + 1 < EPG) {
            zv = __ldg(&zb[s_src[e + 1] * HH + tid]);
            ev = __ldg(&eeact[(size_t)s_u[e + 1] * HH + tid]);
        }
        sagg[d * HH + tid] += cur;
    }
    __syncthreads();

    __nv_bfloat16* oh = aggh + (size_t)b * NPG * HH + tid;
    __nv_bfloat16* ol = aggl + (size_t)b * NPG * HH + tid;
#pragma unroll
    for (int n = 0; n < NPG; n++) {
        float v = sagg[n * HH + tid];
        __nv_bfloat16 h = __float2bfloat16(v);
        __nv_bfloat16 l = __float2bfloat16(v - __bfloat162float(h));
        oh[n * HH] = h;
        ol[n * HH] = l;
    }
}
#define AGG_SMEM (NPG * HH * (int)sizeof(float))

// ---------------- weight transpose + split (batched over grid.z) ----------------
__global__ void transpose_split(const float* __restrict__ S,
                                __nv_bfloat16* __restrict__ Dh,
                                __nv_bfloat16* __restrict__ Dl, int K, int N) {
    __shared__ float t[32][33];
    size_t moff = (size_t)blockIdx.z * K * N;
    S += moff; Dh += moff; Dl += moff;
    int k0 = blockIdx.y * 32, n0 = blockIdx.x * 32;
    int x = threadIdx.x, y = threadIdx.y;
#pragma unroll
    for (int i = 0; i < 32; i += 8) t[y + i][x] = S[(size_t)(k0 + y + i) * N + n0 + x];
    __syncthreads();
#pragma unroll
    for (int i = 0; i < 32; i += 8) {
        float v = t[x][y + i];
        __nv_bfloat16 h = __float2bfloat16(v);
        __nv_bfloat16 l = __float2bfloat16(v - __bfloat162float(h));
        Dh[(size_t)(n0 + y + i) * K + k0 + x] = h;
        Dl[(size_t)(n0 + y + i) * K + k0 + x] = l;
    }
}

// ---------------- split / bn passes ----------------
__global__ void split_f32(const float* __restrict__ X,
                          __nv_bfloat16* __restrict__ Xh, __nv_bfloat16* __restrict__ Xl,
                          size_t total4) {
    size_t i = (size_t)blockIdx.x * blockDim.x + threadIdx.x;
    if (i >= total4) return;
    uint2 hi, lo;
    split4(((const float4*)X)[i], hi, lo);
    ((uint2*)Xh)[i] = hi;
    ((uint2*)Xl)[i] = lo;
}

__global__ void bn_relu_split(const float* __restrict__ X,
                              __nv_bfloat16* __restrict__ Xh, __nv_bfloat16* __restrict__ Xl,
                              size_t total4, int cols, const float* __restrict__ bnp) {
    size_t i = (size_t)blockIdx.x * blockDim.x + threadIdx.x;
    if (i >= total4) return;
    int c = (int)((i * 4) % cols);
    float4 x = ((const float4*)X)[i];
    float4 y;
    y.x = fmaxf(0.f, x.x * bnp[c + 0] + bnp[1024 + c + 0]);
    y.y = fmaxf(0.f, x.y * bnp[c + 1] + bnp[1024 + c + 1]);
    y.z = fmaxf(0.f, x.z * bnp[c + 2] + bnp[1024 + c + 2]);
    y.w = fmaxf(0.f, x.w * bnp[c + 3] + bnp[1024 + c + 3]);
    uint2 hi, lo;
    split4(y, hi, lo);
    ((uint2*)Xh)[i] = hi;
    ((uint2*)Xl)[i] = lo;
}

// ---------------- embeddings / batched bond path ----------------
__global__ void embed_nodes(const int* __restrict__ x, const float* __restrict__ tab,
                            float* __restrict__ z) {
    int n = blockIdx.x;
    __shared__ int idx[9];
    if (threadIdx.x < 9) idx[threadIdx.x] = x[n * 9 + threadIdx.x] + c_node_off[threadIdx.x];
    __syncthreads();
    for (int c = threadIdx.x; c < HH; c += blockDim.x) {
        float acc = 0.f;
#pragma unroll
        for (int f = 0; f < 9; f++) acc += tab[(size_t)idx[f] * HH + c];
        z[(size_t)n * HH + c] = acc;
    }
}

__global__ void combo_hist(const int* __restrict__ ea, int* __restrict__ combo,
                           int* __restrict__ cnt) {
    int e = blockIdx.x * 256 + threadIdx.x;
    if (e >= EE) return;
    int c = ea[e * 3] * 12 + ea[e * 3 + 1] * 2 + ea[e * 3 + 2];
    combo[e] = c;
    atomicAdd(&cnt[c], 1);
}

__global__ void embed_edges_u(const float* __restrict__ tab, float* __restrict__ embu) {
    int u = blockIdx.x;
    int a0 = u / 12, a1 = (u % 12) / 2, a2 = u & 1;
    int c = threadIdx.x;
    embu[u * HEH + c] = tab[(size_t)a0 * HEH + c]
                      + tab[(size_t)(119 + a1) * HEH + c]
                      + tab[(size_t)(128 + a2) * HEH + c];
}

__global__ void bond_small(const float* __restrict__ embu, const float* __restrict__ bondW,
                           const float* __restrict__ bondB, float* __restrict__ eeu) {
    __shared__ float se[HEH];
    int u = blockIdx.x, l = blockIdx.y;
    const float* bW = bondW + (size_t)l * HEH * HH;
    if (threadIdx.x < HEH) se[threadIdx.x] = embu[u * HEH + threadIdx.x];
    __syncthreads();
    int c = threadIdx.x;
    float acc = bondB[l * HH + c];
#pragma unroll 4
    for (int k = 0; k < HEH; k++) acc += se[k] * bW[(size_t)k * HH + c];
    eeu[((size_t)l * NCOMBO + u) * HH + c] = acc;
}

__global__ void wstats(const float* __restrict__ eeu, const int* __restrict__ cnt,
                       float* __restrict__ estats) {
    int l = blockIdx.y;
    int c = blockIdx.x * 256 + threadIdx.x;
    const float* base = eeu + (size_t)l * NCOMBO * HH;
    float m = 0.f, q = 0.f;
    for (int u = 0; u < NCOMBO; u++) {
        float w = (float)cnt[u];
        float v = base[u * HH + c];
        m += w * v;
        q += w * v * v;
    }
    estats[l * 2048 + c] = m;
    estats[l * 2048 + 1024 + c] = q;
}

__global__ void bn_prep_e(float* __restrict__ estats, const float* __restrict__ g,
                          const float* __restrict__ b) {
    int l = blockIdx.y;
    int c = blockIdx.x * 256 + threadIdx.x;
    float* st = estats + l * 2048;
    float m = st[c] * (1.f / EE);
    float var = st[1024 + c] * (1.f / EE) - m * m;
    float sc = g[l * HH + c] * rsqrtf(var + EPSV);
    st[c] = sc;
    st[1024 + c] = b[l * HH + c] - m * sc;
}

__global__ void eeact_apply(const float* __restrict__ eeu, const float* __restrict__ estats,
                            float* __restrict__ eeact) {
    int u = blockIdx.x, l = blockIdx.y;
    int c = threadIdx.x;
    const float* st = estats + l * 2048;
    size_t i = ((size_t)l * NCOMBO + u) * HH + c;
    eeact[i] = fmaxf(0.f, eeu[i] * st[c] + st[1024 + c]);
}

__global__ void bn_prep2(float* __restrict__ stats, float* __restrict__ bnp, int cols,
                         float inv_rows, const float* __restrict__ g,
                         const float* __restrict__ b) {
    int c = blockIdx.x * blockDim.x + threadIdx.x;
    if (c >= cols) return;
    float m = stats[c] * inv_rows;
    float var = stats[1024 + c] * inv_rows - m * m;
    float sc = g[c] * rsqrtf(var + EPSV);
    bnp[c] = sc;
    bnp[1024 + c] = b[c] - m * sc;
    stats[c] = 0.f;
    stats[1024 + c] = 0.f;
}

// ---------------- collapsed output head ----------------
__global__ void att_vec(const float* __restrict__ gapW, const float* __restrict__ gapB,
                        const float* __restrict__ attW, const float* __restrict__ attB,
                        float* __restrict__ v) {
    int w = blockIdx.x * (blockDim.x / 32) + (threadIdx.x / 32);
    int lane = threadIdx.x & 31;
    if (w > OUTD) return;
    const float* row = (w < OUTD) ? (gapW + (size_t)w * HH) : gapB;
    float acc = 0.f;
    for (int h = lane; h < HH; h += 32) acc += row[h] * attW[h];
#pragma unroll
    for (int o = 16; o; o >>= 1) acc += __shfl_xor_sync(0xffffffffu, acc, o);
    if (lane == 0) v[w] = acc + ((w == OUTD) ? attB[0] : 0.f);
}

__global__ void att_w(const float* __restrict__ outW, const float* __restrict__ outB,
                      const float* __restrict__ v, float* __restrict__ w) {
    int r = blockIdx.x * 8 + (threadIdx.x >> 5);
    int lane = threadIdx.x & 31;
    if (r > HH) return;
    const float* row = (r < HH) ? (outW + (size_t)r * OUTD) : outB;
    float acc = 0.f;
    for (int j = lane; j < OUTD; j += 32) acc += row[j] * v[j];
#pragma unroll
    for (int o = 16; o; o >>= 1) acc += __shfl_xor_sync(0xffffffffu, acc, o);
    if (lane == 0) w[r] = acc + ((r == HH) ? v[OUTD] : 0.f);
}

__global__ void __launch_bounds__(256)
pool_z(const float* __restrict__ zpre, const float* __restrict__ bnp,
       const float* __restrict__ w,
       __nv_bfloat16* __restrict__ zgh, __nv_bfloat16* __restrict__ zgl) {
    __shared__ float satt[NPG];
    __shared__ float salpha[NPG];
    int b = blockIdx.x;
    int warp = threadIdx.x >> 5, lane = threadIdx.x & 31;
    const float cst = w[HH];
    const float* zb = zpre + (size_t)b * NPG * HH;

    for (int n = warp; n < NPG; n += 8) {
        float acc = 0.f;
        for (int k = lane; k < HH; k += 32) {
            float zz = fmaxf(0.f, zb[n * HH + k] * bnp[k] + bnp[1024 + k]);
            acc += zz * w[k];
        }
#pragma unroll
        for (int o = 16; o; o >>= 1) acc += __shfl_xor_sync(0xffffffffu, acc, o);
        if (lane == 0) satt[n] = acc + cst;
    }
    __syncthreads();
    if (threadIdx.x < 32) {
        float a = satt[threadIdx.x];
        float mx = a;
#pragma unroll
        for (int o = 16; o; o >>= 1) mx = fmaxf(mx, __shfl_xor_sync(0xffffffffu, mx, o));
        float ex = expf(a - mx);
        float sm = ex;
#pragma unroll
        for (int o = 16; o; o >>= 1) sm += __shfl_xor_sync(0xffffffffu, sm, o);
        salpha[threadIdx.x] = ex / sm;
    }
    __syncthreads();
    for (int j = threadIdx.x; j < HH; j += 256) {
        float sc = bnp[j], sh = bnp[1024 + j];
        float acc = 0.f;
#pragma unroll
        for (int n = 0; n < NPG; n++)
            acc += salpha[n] * fmaxf(0.f, zb[n * HH + j] * sc + sh);
        __nv_bfloat16 h = __float2bfloat16(acc);
        zgh[(size_t)b * HH + j] = h;
        zgl[(size_t)b * HH + j] = __float2bfloat16(acc - __bfloat162float(h));
    }
}

// ---------------- host orchestration ----------------
extern "C" void kernel_launch(void* const* d_in, const int* in_sizes, int n_in,
                              void* d_out, int out_size) {
    const int*   x        = (const int*)  d_in[0];
    const int*   edgeattr = (const int*)  d_in[1];
    const int*   eidx     = (const int*)  d_in[2];
    const float* node_tab = (const float*)d_in[4];
    const float* edge_tab = (const float*)d_in[5];
    const float* bondW    = (const float*)d_in[6];
    const float* bondB    = (const float*)d_in[7];
    const float* bondG    = (const float*)d_in[8];
    const float* bondBeta = (const float*)d_in[9];
    const float* atomW1   = (const float*)d_in[10];
    const float* atomB1   = (const float*)d_in[11];
    const float* atomG    = (const float*)d_in[12];
    const float* atomBeta = (const float*)d_in[13];
    const float* atomW2   = (const float*)d_in[14];
    const float* atomB2   = (const float*)d_in[15];
    const float* normG    = (const float*)d_in[16];
    const float* normB    = (const float*)d_in[17];
    const float* outW     = (const float*)d_in[18];
    const float* outB     = (const float*)d_in[19];
    const float* gapW     = (const float*)d_in[20];
    const float* gapB     = (const float*)d_in[21];
    const float* attW     = (const float*)d_in[22];
    const float* attB     = (const float*)d_in[23];
    const float* projW    = (const float*)d_in[24];
    const float* projB    = (const float*)d_in[25];
    float* out = (float*)d_out;

    float *p_z, *p_h, *p_zpre, *p_v, *p_w, *p_hgpre, *p_stats, *p_estats;
    float *p_embu, *p_eeu, *p_eeact;
    int *p_combo, *p_cnt;
    __nv_bfloat16 *p_aggh, *p_aggl, *p_zh, *p_zl, *p_zgh, *p_zgl, *p_hgh, *p_hgl;
    __nv_bfloat16 *p_aW1h, *p_aW1l, *p_aW2h, *p_aW2l, *p_oWh, *p_oWl, *p_pWh, *p_pWl;
    cudaGetSymbolAddress((void**)&p_z, g_z);
    cudaGetSymbolAddress((void**)&p_h, g_h);
    cudaGetSymbolAddress((void**)&p_zpre, g_zpre);
    cudaGetSymbolAddress((void**)&p_v, g_v);
    cudaGetSymbolAddress((void**)&p_w, g_w);
    cudaGetSymbolAddress((void**)&p_hgpre, g_hgpre);
    cudaGetSymbolAddress((void**)&p_stats, g_stats);
    cudaGetSymbolAddress((void**)&p_estats, g_estats);
    cudaGetSymbolAddress((void**)&p_combo, g_combo);
    cudaGetSymbolAddress((void**)&p_cnt, g_cnt);
    cudaGetSymbolAddress((void**)&p_embu, g_embu);
    cudaGetSymbolAddress((void**)&p_eeu, g_eeu);
    cudaGetSymbolAddress((void**)&p_eeact, g_eeact);
    cudaGetSymbolAddress((void**)&p_aggh, g_aggh);
    cudaGetSymbolAddress((void**)&p_aggl, g_aggl);
    cudaGetSymbolAddress((void**)&p_zh, g_zh);
    cudaGetSymbolAddress((void**)&p_zl, g_zl);
    cudaGetSymbolAddress((void**)&p_zgh, g_zgh);
    cudaGetSymbolAddress((void**)&p_zgl, g_zgl);
    cudaGetSymbolAddress((void**)&p_hgh, g_hgh);
    cudaGetSymbolAddress((void**)&p_hgl, g_hgl);
    cudaGetSymbolAddress((void**)&p_aW1h, g_aW1h);
    cudaGetSymbolAddress((void**)&p_aW1l, g_aW1l);
    cudaGetSymbolAddress((void**)&p_aW2h, g_aW2h);
    cudaGetSymbolAddress((void**)&p_aW2l, g_aW2l);
    cudaGetSymbolAddress((void**)&p_oWh, g_oWh);
    cudaGetSymbolAddress((void**)&p_oWl, g_oWl);
    cudaGetSymbolAddress((void**)&p_pWh, g_pWh);
    cudaGetSymbolAddress((void**)&p_pWl, g_pWl);

    float* stats1 = p_stats;
    float* stats2 = p_stats + 2048;
    float* bnp1   = p_stats + 4096;
    float* bnp2   = p_stats + 6144;

    cudaFuncSetAttribute(gemm_mma<true , false>, cudaFuncAttributeMaxDynamicSharedMemorySize, GEMM_SMEM);
    cudaFuncSetAttribute(gemm_mma<true , true >, cudaFuncAttributeMaxDynamicSharedMemorySize, GEMM_SMEM);
    cudaFuncSetAttribute(gemm_mma<false, false>, cudaFuncAttributeMaxDynamicSharedMemorySize, GEMM_SMEM);
    cudaFuncSetAttribute(graph_aggregate<false>, cudaFuncAttributeMaxDynamicSharedMemorySize, AGG_SMEM);
    cudaFuncSetAttribute(graph_aggregate<true >, cudaFuncAttributeMaxDynamicSharedMemorySize, AGG_SMEM);

    // batched weight transposes + bf16 split
    transpose_split<<<dim3(H2 / 32, HH / 32, LL), dim3(32, 8)>>>(atomW1, p_aW1h, p_aW1l, HH, H2);
    transpose_split<<<dim3(HH / 32, H2 / 32, LL), dim3(32, 8)>>>(atomW2, p_aW2h, p_aW2l, H2, HH);
    transpose_split<<<dim3(OUTD / 32, HH / 32, 1), dim3(32, 8)>>>(outW, p_oWh, p_oWl, HH, OUTD);
    transpose_split<<<dim3(OUTD / 32, OUTD / 32, 1), dim3(32, 8)>>>(projW, p_pWh, p_pWl, OUTD, OUTD);

    // output-head vectors
    att_vec<<<129, 256>>>(gapW, gapB, attW, attB, p_v);
    att_w<<<65, 256>>>(outW, outB, p_v, p_w);

    // embeddings + edge combo machinery
    embed_nodes<<<NN, 256>>>(x, node_tab, p_z);
    cudaMemsetAsync(p_cnt, 0, NCOMBO * sizeof(int));
    cudaMemsetAsync(p_stats, 0, 4096 * sizeof(float));
    combo_hist<<<(EE + 255) / 256, 256>>>(edgeattr, p_combo, p_cnt);
    embed_edges_u<<<NCOMBO, HEH>>>(edge_tab, p_embu);

    // precompute ALL layers' bond tables
    bond_small<<<dim3(NCOMBO, LL), HH>>>(p_embu, bondW, bondB, p_eeu);
    wstats<<<dim3(2, LL), 256>>>(p_eeu, p_cnt, p_estats);
    bn_prep_e<<<dim3(2, LL), 256>>>(p_estats, bondG, bondBeta);
    eeact_apply<<<dim3(NCOMBO, LL), HH>>>(p_eeu, p_estats, p_eeact);

    for (int l = 0; l < LL; l++) {
        const __nv_bfloat16* aW1h = p_aW1h + (size_t)l * H2 * HH;
        const __nv_bfloat16* aW1l = p_aW1l + (size_t)l * H2 * HH;
        const float* aB1  = atomB1   + (size_t)l * H2;
        const float* aG   = atomG    + (size_t)l * H2;
        const float* aBe  = atomBeta + (size_t)l * H2;
        const __nv_bfloat16* aW2h = p_aW2h + (size_t)l * HH * H2;
        const __nv_bfloat16* aW2l = p_aW2l + (size_t)l * HH * H2;
        const float* aB2  = atomB2   + (size_t)l * HH;
        const float* nG   = normG    + (size_t)l * HH;
        const float* nB   = normB    + (size_t)l * HH;
        const float* eea  = p_eeact + (size_t)l * NCOMBO * HH;

        if (l == 0)
            graph_aggregate<false><<<BB, 512, AGG_SMEM>>>(
                p_z, nullptr, eea, eidx, p_combo, p_aggh, p_aggl);
        else
            graph_aggregate<true><<<BB, 512, AGG_SMEM>>>(
                p_zpre, bnp2, eea, eidx, p_combo, p_aggh, p_aggl);

        // h_pre = agg @ aW1 + aB1, stats fused
        gemm_mma<true, false><<<dim3(H2 / 128, NN / 128), 256, GEMM_SMEM>>>(
            H2, HH, p_aggh, p_aggl, nullptr, nullptr, aW1h, aW1l, aB1, p_h, stats1);
        bn_prep2<<<4, 256>>>(stats1, bnp1, H2, 1.f / NN, aG, aBe);

        // z_pre = relu(bn(h_pre)) @ aW2 + aB2 — BN+ReLU+split fused on A fill
        gemm_mma<true, true><<<dim3(HH / 128, NN / 128), 256, GEMM_SMEM>>>(
            HH, H2, nullptr, nullptr, p_h, bnp1, aW2h, aW2l, aB2, p_zpre, stats2);
        bn_prep2<<<2, 256>>>(stats2, bnp2, HH, 1.f / NN, nG, nB);
    }

    // collapsed head
    pool_z<<<BB, 256>>>(p_zpre, bnp2, p_w, p_zgh, p_zgl);

    gemm_mma<false, false><<<dim3(OUTD / 128, BB / 128), 256, GEMM_SMEM>>>(
        OUTD, HH, p_zgh, p_zgl, nullptr, nullptr, p_oWh, p_oWl, outB, p_hgpre, nullptr);

    split_f32<<<(unsigned)(((size_t)BB * OUTD / 4 + 255) / 256), 256>>>(
        p_hgpre, p_hgh, p_hgl, (size_t)BB * OUTD / 4);

    gemm_mma<false, false><<<dim3(OUTD / 128, BB / 128), 256, GEMM_SMEM>>>(
        OUTD, OUTD, p_hgh, p_hgl, nullptr, nullptr, p_pWh, p_pWl, projB, out, nullptr);
}

// round 13
// speedup vs baseline: 1.0196x; 1.0196x over previous
#include <cuda_runtime.h>
#include <cuda_bf16.h>
#include <cstdint>

// ---------------- problem constants ----------------
#define NN      32768
#define EE      131072
#define HH      512
#define HEH     128
#define H2      1024
#define OUTD    1024
#define BB      1024
#define NPG     32
#define EPG     128
#define LL      6
#define EPSV    1e-5f
#define NCOMBO  264

__device__ __constant__ int c_node_off[9] = {0,119,128,139,151,160,165,173,175};

// ---------------- scratch (device globals; no allocs allowed) ----------------
__device__ float g_z    [(size_t)NN * HH];
__device__ float g_h    [(size_t)NN * H2];
__device__ float g_zpre [(size_t)NN * HH];
__device__ float g_v    [OUTD + 1];
__device__ float g_w    [HH + 1];
__device__ float g_hgpre[(size_t)BB * OUTD];
__device__ float g_stats[8192];      // stats1, stats2, bnp1, (spare)
__device__ float g_estats[LL * 2048];
__device__ int   g_combo[EE];
__device__ int   g_cnt  [NCOMBO];
__device__ float g_embu [NCOMBO * HEH];
__device__ float g_eeu  [(size_t)LL * NCOMBO * HH];
__device__ float g_eeact[(size_t)LL * NCOMBO * HH];
__device__ __nv_bfloat16 g_aggh[(size_t)NN * HH];
__device__ __nv_bfloat16 g_aggl[(size_t)NN * HH];
__device__ __nv_bfloat16 g_hh  [(size_t)NN * H2];
__device__ __nv_bfloat16 g_hl  [(size_t)NN * H2];
__device__ __nv_bfloat16 g_zgh [(size_t)BB * HH];
__device__ __nv_bfloat16 g_zgl [(size_t)BB * HH];
__device__ __nv_bfloat16 g_hgh [(size_t)BB * OUTD];
__device__ __nv_bfloat16 g_hgl [(size_t)BB * OUTD];
__device__ __nv_bfloat16 g_aW1h[(size_t)LL * H2 * HH];
__device__ __nv_bfloat16 g_aW1l[(size_t)LL * H2 * HH];
__device__ __nv_bfloat16 g_aW2h[(size_t)LL * HH * H2];
__device__ __nv_bfloat16 g_aW2l[(size_t)LL * HH * H2];
__device__ __nv_bfloat16 g_oWh [(size_t)OUTD * HH];
__device__ __nv_bfloat16 g_oWl [(size_t)OUTD * HH];
__device__ __nv_bfloat16 g_pWh [(size_t)OUTD * OUTD];
__device__ __nv_bfloat16 g_pWl [(size_t)OUTD * OUTD];

// ---------------- asm helpers ----------------
__device__ __forceinline__ uint32_t smem_u32(const void* p) {
    uint32_t a;
    asm("{ .reg .u64 t; cvta.to.shared.u64 t, %1; cvt.u32.u64 %0, t; }" : "=r"(a) : "l"(p));
    return a;
}
__device__ __forceinline__ void ldm_x4(uint32_t* r, uint32_t addr) {
    asm volatile("ldmatrix.sync.aligned.m8n8.x4.shared.b16 {%0,%1,%2,%3}, [%4];"
                 : "=r"(r[0]), "=r"(r[1]), "=r"(r[2]), "=r"(r[3]) : "r"(addr));
}
__device__ __forceinline__ void mma_bf16(float* c, const uint32_t* a, const uint32_t* b) {
    asm volatile("mma.sync.aligned.m16n8k16.row.col.f32.bf16.bf16.f32 "
                 "{%0,%1,%2,%3}, {%4,%5,%6,%7}, {%8,%9}, {%0,%1,%2,%3};"
                 : "+f"(c[0]), "+f"(c[1]), "+f"(c[2]), "+f"(c[3])
                 : "r"(a[0]), "r"(a[1]), "r"(a[2]), "r"(a[3]), "r"(b[0]), "r"(b[1]));
}
__device__ __forceinline__ void cpasync16(uint32_t sa, const void* ga) {
    asm volatile("cp.async.cg.shared.global [%0], [%1], 16;" :: "r"(sa), "l"(ga));
}
#define CP_COMMIT() asm volatile("cp.async.commit_group;" ::: "memory")
#define CP_WAIT1()  asm volatile("cp.async.wait_group 1;" ::: "memory")

__device__ __forceinline__ uint32_t pk(__nv_bfloat16 a, __nv_bfloat16 b) {
    return (uint32_t)__bfloat16_as_ushort(a) | ((uint32_t)__bfloat16_as_ushort(b) << 16);
}
__device__ __forceinline__ void split4(float4 v, uint2& hi, uint2& lo) {
    __nv_bfloat16 h0 = __float2bfloat16(v.x), h1 = __float2bfloat16(v.y);
    __nv_bfloat16 h2 = __float2bfloat16(v.z), h3 = __float2bfloat16(v.w);
    __nv_bfloat16 l0 = __float2bfloat16(v.x - __bfloat162float(h0));
    __nv_bfloat16 l1 = __float2bfloat16(v.y - __bfloat162float(h1));
    __nv_bfloat16 l2 = __float2bfloat16(v.z - __bfloat162float(h2));
    __nv_bfloat16 l3 = __float2bfloat16(v.w - __bfloat162float(h3));
    hi = make_uint2(pk(h0, h1), pk(h2, h3));
    lo = make_uint2(pk(l0, l1), pk(l2, l3));
}
__device__ __forceinline__ void bn_from_stats(const float* __restrict__ stats, int c,
                                              float inv_rows, const float* __restrict__ g,
                                              const float* __restrict__ b,
                                              float& sc, float& sh) {
    float m = stats[c] * inv_rows;
    float var = stats[1024 + c] * inv_rows - m * m;
    sc = g[c] * rsqrtf(var + EPSV);
    sh = b[c] - m * sc;
}

// SMEM tile: 128 rows x 32 bf16 = 64B/row, XOR chunk swizzle
#define TILEB  (128 * 64)
#define STAGEB (4 * TILEB)
#define NSTAGE 3
#define GEMM_SMEM (NSTAGE * STAGEB)

__device__ __forceinline__ uint32_t swz(int row, int chunk) {
    return (uint32_t)(row * 64 + (((chunk + (row >> 1)) & 3) << 4));
}

// ---------------- tensor-core GEMM (R10 config: proven best) ----------------
template <bool STATS>
__global__ void __launch_bounds__(256, 2)
gemm_mma(int N, int K,
         const __nv_bfloat16* __restrict__ Ah, const __nv_bfloat16* __restrict__ Al,
         const __nv_bfloat16* __restrict__ Bh, const __nv_bfloat16* __restrict__ Bl,
         const float* __restrict__ bias, float* __restrict__ C,
         float* __restrict__ stats) {
    extern __shared__ char smem[];

    const int tid = threadIdx.x, lane = tid & 31, wid = tid >> 5;
    const int wr = wid >> 2, wc = wid & 3;
    const int brow = blockIdx.y, bcol = blockIdx.x;

    const size_t Kb = (size_t)K * 2;
    const char* pAh = (const char*)(Ah + (size_t)brow * 128 * K);
    const char* pAl = (const char*)(Al + (size_t)brow * 128 * K);
    const char* pBh = (const char*)(Bh + (size_t)bcol * 128 * K);
    const char* pBl = (const char*)(Bl + (size_t)bcol * 128 * K);

    const uint32_t ubase = smem_u32(smem);
    const int lr0 = tid >> 2, lc0 = tid & 3;
    const int lr1 = lr0 + 64, lc1 = lc0;
    const uint32_t so0 = swz(lr0, lc0), so1 = swz(lr1, lc1);

    auto issue = [&](int k0, int s) {
        uint32_t base = ubase + s * STAGEB;
        size_t g0 = (size_t)lr0 * Kb + (size_t)k0 * 64 + lc0 * 16;
        size_t g1 = (size_t)lr1 * Kb + (size_t)k0 * 64 + lc1 * 16;
        cpasync16(base + so0,             pAh + g0);
        cpasync16(base + so1,             pAh + g1);
        cpasync16(base + TILEB + so0,     pAl + g0);
        cpasync16(base + TILEB + so1,     pAl + g1);
        cpasync16(base + 2 * TILEB + so0, pBh + g0);
        cpasync16(base + 2 * TILEB + so1, pBh + g1);
        cpasync16(base + 3 * TILEB + so0, pBl + g0);
        cpasync16(base + 3 * TILEB + so1, pBl + g1);
    };

    float acc[4][4][4];
#pragma unroll
    for (int i = 0; i < 4; i++)
#pragma unroll
        for (int j = 0; j < 4; j++)
#pragma unroll
            for (int q = 0; q < 4; q++) acc[i][j][q] = 0.f;

    const int a_row = (lane & 15);
    const int a_c   = (lane >> 4);
    const int b_row = (lane & 7) + ((lane >> 4) << 3);
    const int b_c   = ((lane >> 3) & 1);

    auto compute = [&](int s) {
        uint32_t uAh = ubase + s * STAGEB;
        uint32_t uAl = uAh + TILEB, uBh = uAl + TILEB, uBl = uBh + TILEB;
#pragma unroll
        for (int ks = 0; ks < 2; ks++) {
            uint32_t ah[4][4], al[4][4];
#pragma unroll
            for (int mt = 0; mt < 4; mt++) {
                int row = wr * 64 + mt * 16 + a_row;
                uint32_t off = swz(row, 2 * ks + a_c);
                ldm_x4(ah[mt], uAh + off);
                ldm_x4(al[mt], uAl + off);
            }
            uint32_t bh[4][2], bl[4][2];
#pragma unroll
            for (int np = 0; np < 2; np++) {
                int row = wc * 32 + np * 16 + b_row;
                uint32_t off = swz(row, 2 * ks + b_c);
                uint32_t r[4];
                ldm_x4(r, uBh + off);
                bh[np * 2][0] = r[0]; bh[np * 2][1] = r[1];
                bh[np * 2 + 1][0] = r[2]; bh[np * 2 + 1][1] = r[3];
                ldm_x4(r, uBl + off);
                bl[np * 2][0] = r[0]; bl[np * 2][1] = r[1];
                bl[np * 2 + 1][0] = r[2]; bl[np * 2 + 1][1] = r[3];
            }
#pragma unroll
            for (int mt = 0; mt < 4; mt++)
#pragma unroll
                for (int nt = 0; nt < 4; nt++) {
                    mma_bf16(acc[mt][nt], ah[mt], bh[nt]);
                    mma_bf16(acc[mt][nt], ah[mt], bl[nt]);
                    mma_bf16(acc[mt][nt], al[mt], bh[nt]);
                }
        }
    };

    const int nk = K >> 5;
    issue(0, 0); CP_COMMIT();
    issue(1, 1); CP_COMMIT();
    CP_WAIT1();
    __syncthreads();
    int s = 0, snext = 2;
    for (int k = 0; k < nk; k++) {
        compute(s);
        if (k + 2 < nk) issue(k + 2, snext);
        CP_COMMIT();
        CP_WAIT1();
        __syncthreads();
        s = (s == 2) ? 0 : s + 1;
        snext = (snext == 2) ? 0 : snext + 1;
    }

    float s1[8], s2[8];
    if (STATS) {
#pragma unroll
        for (int j = 0; j < 8; j++) { s1[j] = 0.f; s2[j] = 0.f; }
    }
#pragma unroll
    for (int mt = 0; mt < 4; mt++) {
        int row0 = brow * 128 + wr * 64 + mt * 16 + (lane >> 2);
#pragma unroll
        for (int nt = 0; nt < 4; nt++) {
            int col = bcol * 128 + wc * 32 + nt * 8 + (lane & 3) * 2;
            float b0 = bias[col], b1 = bias[col + 1];
            float v00 = acc[mt][nt][0] + b0, v01 = acc[mt][nt][1] + b1;
            float v10 = acc[mt][nt][2] + b0, v11 = acc[mt][nt][3] + b1;
            *(float2*)(C + (size_t)row0 * N + col) = make_float2(v00, v01);
            *(float2*)(C + (size_t)(row0 + 8) * N + col) = make_float2(v10, v11);
            if (STATS) {
                s1[nt * 2 + 0] += v00 + v10;
                s1[nt * 2 + 1] += v01 + v11;
                s2[nt * 2 + 0] += v00 * v00 + v10 * v10;
                s2[nt * 2 + 1] += v01 * v01 + v11 * v11;
            }
        }
    }
    if (STATS) {
#pragma unroll
        for (int j = 0; j < 8; j++) {
#pragma unroll
            for (int o = 4; o <= 16; o <<= 1) {
                s1[j] += __shfl_xor_sync(0xffffffffu, s1[j], o);
                s2[j] += __shfl_xor_sync(0xffffffffu, s2[j], o);
            }
        }
        if (lane < 4) {
#pragma unroll
            for (int nt = 0; nt < 4; nt++) {
#pragma unroll
                for (int p = 0; p < 2; p++) {
                    int col = bcol * 128 + wc * 32 + nt * 8 + lane * 2 + p;
                    atomicAdd(&stats[col], s1[nt * 2 + p]);
                    atomicAdd(&stats[1024 + col], s2[nt * 2 + p]);
                }
            }
        }
    }
}

// ---------------- per-graph aggregation (BN params computed in-thread from stats) ----------------
template <bool BN>
__global__ void __launch_bounds__(512, 2)
graph_aggregate(const float* __restrict__ zsrc, const float* __restrict__ stats,
                const float* __restrict__ gg, const float* __restrict__ bb,
                const float* __restrict__ eeact,
                const int* __restrict__ eidx, const int* __restrict__ combo,
                __nv_bfloat16* __restrict__ aggh, __nv_bfloat16* __restrict__ aggl) {
    extern __shared__ float sagg[];
    __shared__ int s_src[EPG], s_dst[EPG], s_u[EPG];

    const int b = blockIdx.x;
    const int tid = threadIdx.x;

    float sc = 1.f, sh = 0.f;
    if (BN) bn_from_stats(stats, tid, 1.f / NN, gg, bb, sc, sh);

    if (tid < EPG) {
        s_src[tid] = eidx[b * EPG + tid] - b * NPG;
        s_dst[tid] = eidx[EE + b * EPG + tid] - b * NPG;
        s_u[tid]   = combo[b * EPG + tid];
    }
    const float* zb = zsrc + (size_t)b * NPG * HH;
#pragma unroll
    for (int n = 0; n < NPG; n++) {
        float v = zb[n * HH + tid];
        if (BN) v = fmaxf(0.f, v * sc + sh);
        sagg[n * HH + tid] = v;
    }
    __syncthreads();

    float zv = __ldg(&zb[s_src[0] * HH + tid]);
    float ev = __ldg(&eeact[(size_t)s_u[0] * HH + tid]);
#pragma unroll 4
    for (int e = 0; e < EPG; e++) {
        float zcur = zv;
        if (BN) zcur = fmaxf(0.f, zcur * sc + sh);
        float cur = zcur + ev;
        int d = s_dst[e];
        if (e + 1 < EPG) {
            zv = __ldg(&zb[s_src[e + 1] * HH + tid]);
            ev = __ldg(&eeact[(size_t)s_u[e + 1] * HH + tid]);
        }
        sagg[d * HH + tid] += cur;
    }
    __syncthreads();

    __nv_bfloat16* oh = aggh + (size_t)b * NPG * HH + tid;
    __nv_bfloat16* ol = aggl + (size_t)b * NPG * HH + tid;
#pragma unroll
    for (int n = 0; n < NPG; n++) {
        float v = sagg[n * HH + tid];
        __nv_bfloat16 h = __float2bfloat16(v);
        __nv_bfloat16 l = __float2bfloat16(v - __bfloat162float(h));
        oh[n * HH] = h;
        ol[n * HH] = l;
    }
}
#define AGG_SMEM (NPG * HH * (int)sizeof(float))

// ---------------- weight transpose + split (batched over grid.z) ----------------
__global__ void transpose_split(const float* __restrict__ S,
                                __nv_bfloat16* __restrict__ Dh,
                                __nv_bfloat16* __restrict__ Dl, int K, int N) {
    __shared__ float t[32][33];
    size_t moff = (size_t)blockIdx.z * K * N;
    S += moff; Dh += moff; Dl += moff;
    int k0 = blockIdx.y * 32, n0 = blockIdx.x * 32;
    int x = threadIdx.x, y = threadIdx.y;
#pragma unroll
    for (int i = 0; i < 32; i += 8) t[y + i][x] = S[(size_t)(k0 + y + i) * N + n0 + x];
    __syncthreads();
#pragma unroll
    for (int i = 0; i < 32; i += 8) {
        float v = t[x][y + i];
        __nv_bfloat16 h = __float2bfloat16(v);
        __nv_bfloat16 l = __float2bfloat16(v - __bfloat162float(h));
        Dh[(size_t)(n0 + y + i) * K + k0 + x] = h;
        Dl[(size_t)(n0 + y + i) * K + k0 + x] = l;
    }
}

// ---------------- split / bn passes ----------------
__global__ void split_f32(const float* __restrict__ X,
                          __nv_bfloat16* __restrict__ Xh, __nv_bfloat16* __restrict__ Xl,
                          size_t total4) {
    size_t i = (size_t)blockIdx.x * blockDim.x + threadIdx.x;
    if (i >= total4) return;
    uint2 hi, lo;
    split4(((const float4*)X)[i], hi, lo);
    ((uint2*)Xh)[i] = hi;
    ((uint2*)Xl)[i] = lo;
}

// also zeroes zstats (2048 floats) via block 0 — safe: consumed next kernel
__global__ void bn_relu_split(const float* __restrict__ X,
                              __nv_bfloat16* __restrict__ Xh, __nv_bfloat16* __restrict__ Xl,
                              size_t total4, int cols, const float* __restrict__ bnp,
                              float* __restrict__ zstats) {
    if (blockIdx.x == 0) {
        for (int j = threadIdx.x; j < 2048; j += blockDim.x) zstats[j] = 0.f;
    }
    size_t i = (size_t)blockIdx.x * blockDim.x + threadIdx.x;
    if (i >= total4) return;
    int c = (int)((i * 4) % cols);
    float4 x = ((const float4*)X)[i];
    float4 y;
    y.x = fmaxf(0.f, x.x * bnp[c + 0] + bnp[1024 + c + 0]);
    y.y = fmaxf(0.f, x.y * bnp[c + 1] + bnp[1024 + c + 1]);
    y.z = fmaxf(0.f, x.z * bnp[c + 2] + bnp[1024 + c + 2]);
    y.w = fmaxf(0.f, x.w * bnp[c + 3] + bnp[1024 + c + 3]);
    uint2 hi, lo;
    split4(y, hi, lo);
    ((uint2*)Xh)[i] = hi;
    ((uint2*)Xl)[i] = lo;
}

// ---------------- embeddings / batched bond path ----------------
__global__ void embed_nodes(const int* __restrict__ x, const float* __restrict__ tab,
                            float* __restrict__ z) {
    int n = blockIdx.x;
    __shared__ int idx[9];
    if (threadIdx.x < 9) idx[threadIdx.x] = x[n * 9 + threadIdx.x] + c_node_off[threadIdx.x];
    __syncthreads();
    for (int c = threadIdx.x; c < HH; c += blockDim.x) {
        float acc = 0.f;
#pragma unroll
        for (int f = 0; f < 9; f++) acc += tab[(size_t)idx[f] * HH + c];
        z[(size_t)n * HH + c] = acc;
    }
}

__global__ void combo_hist(const int* __restrict__ ea, int* __restrict__ combo,
                           int* __restrict__ cnt) {
    int e = blockIdx.x * 256 + threadIdx.x;
    if (e >= EE) return;
    int c = ea[e * 3] * 12 + ea[e * 3 + 1] * 2 + ea[e * 3 + 2];
    combo[e] = c;
    atomicAdd(&cnt[c], 1);
}

__global__ void embed_edges_u(const float* __restrict__ tab, float* __restrict__ embu) {
    int u = blockIdx.x;
    int a0 = u / 12, a1 = (u % 12) / 2, a2 = u & 1;
    int c = threadIdx.x;
    embu[u * HEH + c] = tab[(size_t)a0 * HEH + c]
                      + tab[(size_t)(119 + a1) * HEH + c]
                      + tab[(size_t)(128 + a2) * HEH + c];
}

__global__ void bond_small(const float* __restrict__ embu, const float* __restrict__ bondW,
                           const float* __restrict__ bondB, float* __restrict__ eeu) {
    __shared__ float se[HEH];
    int u = blockIdx.x, l = blockIdx.y;
    const float* bW = bondW + (size_t)l * HEH * HH;
    if (threadIdx.x < HEH) se[threadIdx.x] = embu[u * HEH + threadIdx.x];
    __syncthreads();
    int c = threadIdx.x;
    float acc = bondB[l * HH + c];
#pragma unroll 4
    for (int k = 0; k < HEH; k++) acc += se[k] * bW[(size_t)k * HH + c];
    eeu[((size_t)l * NCOMBO + u) * HH + c] = acc;
}

__global__ void wstats(const float* __restrict__ eeu, const int* __restrict__ cnt,
                       float* __restrict__ estats) {
    int l = blockIdx.y;
    int c = blockIdx.x * 256 + threadIdx.x;
    const float* base = eeu + (size_t)l * NCOMBO * HH;
    float m = 0.f, q = 0.f;
    for (int u = 0; u < NCOMBO; u++) {
        float w = (float)cnt[u];
        float v = base[u * HH + c];
        m += w * v;
        q += w * v * v;
    }
    estats[l * 2048 + c] = m;
    estats[l * 2048 + 1024 + c] = q;
}

__global__ void bn_prep_e(float* __restrict__ estats, const float* __restrict__ g,
                          const float* __restrict__ b) {
    int l = blockIdx.y;
    int c = blockIdx.x * 256 + threadIdx.x;
    float* st = estats + l * 2048;
    float m = st[c] * (1.f / EE);
    float var = st[1024 + c] * (1.f / EE) - m * m;
    float sc = g[l * HH + c] * rsqrtf(var + EPSV);
    st[c] = sc;
    st[1024 + c] = b[l * HH + c] - m * sc;
}

__global__ void eeact_apply(const float* __restrict__ eeu, const float* __restrict__ estats,
                            float* __restrict__ eeact) {
    int u = blockIdx.x, l = blockIdx.y;
    int c = threadIdx.x;
    const float* st = estats + l * 2048;
    size_t i = ((size_t)l * NCOMBO + u) * HH + c;
    eeact[i] = fmaxf(0.f, eeu[i] * st[c] + st[1024 + c]);
}

// bn prep for h (stats1 -> bnp1, re-zero stats1)
__global__ void bn_prep2(float* __restrict__ stats, float* __restrict__ bnp, int cols,
                         float inv_rows, const float* __restrict__ g,
                         const float* __restrict__ b) {
    int c = blockIdx.x * blockDim.x + threadIdx.x;
    if (c >= cols) return;
    float m = stats[c] * inv_rows;
    float var = stats[1024 + c] * inv_rows - m * m;
    float sc = g[c] * rsqrtf(var + EPSV);
    bnp[c] = sc;
    bnp[1024 + c] = b[c] - m * sc;
    stats[c] = 0.f;
    stats[1024 + c] = 0.f;
}

// ---------------- collapsed output head ----------------
__global__ void att_vec(const float* __restrict__ gapW, const float* __restrict__ gapB,
                        const float* __restrict__ attW, const float* __restrict__ attB,
                        float* __restrict__ v) {
    int w = blockIdx.x * (blockDim.x / 32) + (threadIdx.x / 32);
    int lane = threadIdx.x & 31;
    if (w > OUTD) return;
    const float* row = (w < OUTD) ? (gapW + (size_t)w * HH) : gapB;
    float acc = 0.f;
    for (int h = lane; h < HH; h += 32) acc += row[h] * attW[h];
#pragma unroll
    for (int o = 16; o; o >>= 1) acc += __shfl_xor_sync(0xffffffffu, acc, o);
    if (lane == 0) v[w] = acc + ((w == OUTD) ? attB[0] : 0.f);
}

__global__ void att_w(const float* __restrict__ outW, const float* __restrict__ outB,
                      const float* __restrict__ v, float* __restrict__ w) {
    int r = blockIdx.x * 8 + (threadIdx.x >> 5);
    int lane = threadIdx.x & 31;
    if (r > HH) return;
    const float* row = (r < HH) ? (outW + (size_t)r * OUTD) : outB;
    float acc = 0.f;
    for (int j = lane; j < OUTD; j += 32) acc += row[j] * v[j];
#pragma unroll
    for (int o = 16; o; o >>= 1) acc += __shfl_xor_sync(0xffffffffu, acc, o);
    if (lane == 0) w[r] = acc + ((r == HH) ? v[OUTD] : 0.f);
}

// BN params computed per-CTA into smem from stats + g/b
__global__ void __launch_bounds__(256)
pool_z(const float* __restrict__ zpre, const float* __restrict__ stats,
       const float* __restrict__ gg, const float* __restrict__ bb,
       const float* __restrict__ w,
       __nv_bfloat16* __restrict__ zgh, __nv_bfloat16* __restrict__ zgl) {
    __shared__ float satt[NPG];
    __shared__ float salpha[NPG];
    __shared__ float ssc[HH], ssh[HH];
    int b = blockIdx.x;
    int warp = threadIdx.x >> 5, lane = threadIdx.x & 31;
    const float cst = w[HH];
    const float* zb = zpre + (size_t)b * NPG * HH;

    for (int c = threadIdx.x; c < HH; c += 256) {
        float sc, sh;
        bn_from_stats(stats, c, 1.f / NN, gg, bb, sc, sh);
        ssc[c] = sc;
        ssh[c] = sh;
    }
    __syncthreads();

    for (int n = warp; n < NPG; n += 8) {
        float acc = 0.f;
        for (int k = lane; k < HH; k += 32) {
            float zz = fmaxf(0.f, zb[n * HH + k] * ssc[k] + ssh[k]);
            acc += zz * w[k];
        }
#pragma unroll
        for (int o = 16; o; o >>= 1) acc += __shfl_xor_sync(0xffffffffu, acc, o);
        if (lane == 0) satt[n] = acc + cst;
    }
    __syncthreads();
    if (threadIdx.x < 32) {
        float a = satt[threadIdx.x];
        float mx = a;
#pragma unroll
        for (int o = 16; o; o >>= 1) mx = fmaxf(mx, __shfl_xor_sync(0xffffffffu, mx, o));
        float ex = expf(a - mx);
        float sm = ex;
#pragma unroll
        for (int o = 16; o; o >>= 1) sm += __shfl_xor_sync(0xffffffffu, sm, o);
        salpha[threadIdx.x] = ex / sm;
    }
    __syncthreads();
    for (int j = threadIdx.x; j < HH; j += 256) {
        float sc = ssc[j], sh = ssh[j];
        float acc = 0.f;
#pragma unroll
        for (int n = 0; n < NPG; n++)
            acc += salpha[n] * fmaxf(0.f, zb[n * HH + j] * sc + sh);
        __nv_bfloat16 h = __float2bfloat16(acc);
        zgh[(size_t)b * HH + j] = h;
        zgl[(size_t)b * HH + j] = __float2bfloat16(acc - __bfloat162float(h));
    }
}

// ---------------- host orchestration ----------------
extern "C" void kernel_launch(void* const* d_in, const int* in_sizes, int n_in,
                              void* d_out, int out_size) {
    const int*   x        = (const int*)  d_in[0];
    const int*   edgeattr = (const int*)  d_in[1];
    const int*   eidx     = (const int*)  d_in[2];
    const float* node_tab = (const float*)d_in[4];
    const float* edge_tab = (const float*)d_in[5];
    const float* bondW    = (const float*)d_in[6];
    const float* bondB    = (const float*)d_in[7];
    const float* bondG    = (const float*)d_in[8];
    const float* bondBeta = (const float*)d_in[9];
    const float* atomW1   = (const float*)d_in[10];
    const float* atomB1   = (const float*)d_in[11];
    const float* atomG    = (const float*)d_in[12];
    const float* atomBeta = (const float*)d_in[13];
    const float* atomW2   = (const float*)d_in[14];
    const float* atomB2   = (const float*)d_in[15];
    const float* normG    = (const float*)d_in[16];
    const float* normB    = (const float*)d_in[17];
    const float* outW     = (const float*)d_in[18];
    const float* outB     = (const float*)d_in[19];
    const float* gapW     = (const float*)d_in[20];
    const float* gapB     = (const float*)d_in[21];
    const float* attW     = (const float*)d_in[22];
    const float* attB     = (const float*)d_in[23];
    const float* projW    = (const float*)d_in[24];
    const float* projB    = (const float*)d_in[25];
    float* out = (float*)d_out;

    float *p_z, *p_h, *p_zpre, *p_v, *p_w, *p_hgpre, *p_stats, *p_estats;
    float *p_embu, *p_eeu, *p_eeact;
    int *p_combo, *p_cnt;
    __nv_bfloat16 *p_aggh, *p_aggl, *p_hh, *p_hl, *p_zgh, *p_zgl, *p_hgh, *p_hgl;
    __nv_bfloat16 *p_aW1h, *p_aW1l, *p_aW2h, *p_aW2l, *p_oWh, *p_oWl, *p_pWh, *p_pWl;
    cudaGetSymbolAddress((void**)&p_z, g_z);
    cudaGetSymbolAddress((void**)&p_h, g_h);
    cudaGetSymbolAddress((void**)&p_zpre, g_zpre);
    cudaGetSymbolAddress((void**)&p_v, g_v);
    cudaGetSymbolAddress((void**)&p_w, g_w);
    cudaGetSymbolAddress((void**)&p_hgpre, g_hgpre);
    cudaGetSymbolAddress((void**)&p_stats, g_stats);
    cudaGetSymbolAddress((void**)&p_estats, g_estats);
    cudaGetSymbolAddress((void**)&p_combo, g_combo);
    cudaGetSymbolAddress((void**)&p_cnt, g_cnt);
    cudaGetSymbolAddress((void**)&p_embu, g_embu);
    cudaGetSymbolAddress((void**)&p_eeu, g_eeu);
    cudaGetSymbolAddress((void**)&p_eeact, g_eeact);
    cudaGetSymbolAddress((void**)&p_aggh, g_aggh);
    cudaGetSymbolAddress((void**)&p_aggl, g_aggl);
    cudaGetSymbolAddress((void**)&p_hh, g_hh);
    cudaGetSymbolAddress((void**)&p_hl, g_hl);
    cudaGetSymbolAddress((void**)&p_zgh, g_zgh);
    cudaGetSymbolAddress((void**)&p_zgl, g_zgl);
    cudaGetSymbolAddress((void**)&p_hgh, g_hgh);
    cudaGetSymbolAddress((void**)&p_hgl, g_hgl);
    cudaGetSymbolAddress((void**)&p_aW1h, g_aW1h);
    cudaGetSymbolAddress((void**)&p_aW1l, g_aW1l);
    cudaGetSymbolAddress((void**)&p_aW2h, g_aW2h);
    cudaGetSymbolAddress((void**)&p_aW2l, g_aW2l);
    cudaGetSymbolAddress((void**)&p_oWh, g_oWh);
    cudaGetSymbolAddress((void**)&p_oWl, g_oWl);
    cudaGetSymbolAddress((void**)&p_pWh, g_pWh);
    cudaGetSymbolAddress((void**)&p_pWl, g_pWl);

    float* stats1 = p_stats;
    float* stats2 = p_stats + 2048;
    float* bnp1   = p_stats + 4096;

    cudaFuncSetAttribute(gemm_mma<true >, cudaFuncAttributeMaxDynamicSharedMemorySize, GEMM_SMEM);
    cudaFuncSetAttribute(gemm_mma<false>, cudaFuncAttributeMaxDynamicSharedMemorySize, GEMM_SMEM);
    cudaFuncSetAttribute(graph_aggregate<false>, cudaFuncAttributeMaxDynamicSharedMemorySize, AGG_SMEM);
    cudaFuncSetAttribute(graph_aggregate<true >, cudaFuncAttributeMaxDynamicSharedMemorySize, AGG_SMEM);

    // batched weight transposes + bf16 split
    transpose_split<<<dim3(H2 / 32, HH / 32, LL), dim3(32, 8)>>>(atomW1, p_aW1h, p_aW1l, HH, H2);
    transpose_split<<<dim3(HH / 32, H2 / 32, LL), dim3(32, 8)>>>(atomW2, p_aW2h, p_aW2l, H2, HH);
    transpose_split<<<dim3(OUTD / 32, HH / 32, 1), dim3(32, 8)>>>(outW, p_oWh, p_oWl, HH, OUTD);
    transpose_split<<<dim3(OUTD / 32, OUTD / 32, 1), dim3(32, 8)>>>(projW, p_pWh, p_pWl, OUTD, OUTD);

    // output-head vectors
    att_vec<<<129, 256>>>(gapW, gapB, attW, attB, p_v);
    att_w<<<65, 256>>>(outW, outB, p_v, p_w);

    // embeddings + edge combo machinery
    embed_nodes<<<NN, 256>>>(x, node_tab, p_z);
    cudaMemsetAsync(p_cnt, 0, NCOMBO * sizeof(int));
    cudaMemsetAsync(p_stats, 0, 4096 * sizeof(float));
    combo_hist<<<(EE + 255) / 256, 256>>>(edgeattr, p_combo, p_cnt);
    embed_edges_u<<<NCOMBO, HEH>>>(edge_tab, p_embu);

    // precompute ALL layers' bond tables
    bond_small<<<dim3(NCOMBO, LL), HH>>>(p_embu, bondW, bondB, p_eeu);
    wstats<<<dim3(2, LL), 256>>>(p_eeu, p_cnt, p_estats);
    bn_prep_e<<<dim3(2, LL), 256>>>(p_estats, bondG, bondBeta);
    eeact_apply<<<dim3(NCOMBO, LL), HH>>>(p_eeu, p_estats, p_eeact);

    for (int l = 0; l < LL; l++) {
        const __nv_bfloat16* aW1h = p_aW1h + (size_t)l * H2 * HH;
        const __nv_bfloat16* aW1l = p_aW1l + (size_t)l * H2 * HH;
        const float* aB1  = atomB1   + (size_t)l * H2;
        const float* aG   = atomG    + (size_t)l * H2;
        const float* aBe  = atomBeta + (size_t)l * H2;
        const __nv_bfloat16* aW2h = p_aW2h + (size_t)l * HH * H2;
        const __nv_bfloat16* aW2l = p_aW2l + (size_t)l * HH * H2;
        const float* aB2  = atomB2   + (size_t)l * HH;
        const float* eea  = p_eeact + (size_t)l * NCOMBO * HH;

        if (l == 0)
            graph_aggregate<false><<<BB, 512, AGG_SMEM>>>(
                p_z, nullptr, nullptr, nullptr, eea, eidx, p_combo, p_aggh, p_aggl);
        else
            graph_aggregate<true><<<BB, 512, AGG_SMEM>>>(
                p_zpre, stats2, normG + (size_t)(l - 1) * HH, normB + (size_t)(l - 1) * HH,
                eea, eidx, p_combo, p_aggh, p_aggl);

        gemm_mma<true><<<dim3(H2 / 128, NN / 128), 256, GEMM_SMEM>>>(
            H2, HH, p_aggh, p_aggl, aW1h, aW1l, aB1, p_h, stats1);
        bn_prep2<<<4, 256>>>(stats1, bnp1, H2, 1.f / NN, aG, aBe);

        // bn+relu+split of h; also re-zeroes stats2 before gemm2 accumulates
        bn_relu_split<<<(unsigned)(((size_t)NN * H2 / 4 + 255) / 256), 256>>>(
            p_h, p_hh, p_hl, (size_t)NN * H2 / 4, H2, bnp1, stats2);

        gemm_mma<true><<<dim3(HH / 128, NN / 128), 256, GEMM_SMEM>>>(
            HH, H2, p_hh, p_hl, aW2h, aW2l, aB2, p_zpre, stats2);
    }

    // collapsed head (BN params from stats2 + layer-5 norm params, computed in-kernel)
    pool_z<<<BB, 256>>>(p_zpre, stats2,
                        normG + (size_t)(LL - 1) * HH, normB + (size_t)(LL - 1) * HH,
                        p_w, p_zgh, p_zgl);

    gemm_mma<false><<<dim3(OUTD / 128, BB / 128), 256, GEMM_SMEM>>>(
        OUTD, HH, p_zgh, p_zgl, p_oWh, p_oWl, outB, p_hgpre, nullptr);

    split_f32<<<(unsigned)(((size_t)BB * OUTD / 4 + 255) / 256), 256>>>(
        p_hgpre, p_hgh, p_hgl, (size_t)BB * OUTD / 4);

    gemm_mma<false><<<dim3(OUTD / 128, BB / 128), 256, GEMM_SMEM>>>(
        OUTD, OUTD, p_hgh, p_hgl, p_pWh, p_pWl, projB, out, nullptr);
}